// round 8
// baseline (speedup 1.0000x reference)
#include <cuda_runtime.h>
#include <math.h>

// Problem constants
#define TT   1024
#define BB   64
#define DD   512
#define HH   512

// Kernel config
#define NB   128      // CTAs: 4 stages x 32 column-blocks (co-resident on <=148 SMs)
#define NT   512      // threads per CTA (16 warps -> 4 per SMSP)
#define KB   32       // K-block staged in smem (duplicated float2, double-buffered)
#define NKB  16       // 512 / 32

// -------- device scratch (no allocations allowed) --------
__device__ __align__(16) float g_xw0[2][BB * HH];
__device__ __align__(16) float g_xw1[2][BB * HH];
__device__ __align__(16) float g_h0[2][BB * HH];
__device__ __align__(16) float g_h1[2][BB * HH];
__device__ unsigned g_count;

__global__ void rnn_reset_kernel() { g_count = 0u; }

__device__ __forceinline__ void grid_sync(unsigned target) {
    __syncthreads();
    if (threadIdx.x == 0) {
        __threadfence();                 // release all prior global writes
        atomicAdd(&g_count, 1u);
        unsigned v;
        do {
            asm volatile("ld.acquire.gpu.u32 %0, [%1];" : "=r"(v) : "l"(&g_count));
        } while (v < target);
    }
    __syncthreads();
}

// ---- packed fp32x2 helpers (Blackwell packed FP32; only reachable via PTX) ----
__device__ __forceinline__ void ffma2(unsigned long long& d,
                                      unsigned long long a,
                                      unsigned long long b) {
    asm("fma.rn.f32x2 %0, %1, %2, %0;" : "+l"(d) : "l"(a), "l"(b));
}
__device__ __forceinline__ unsigned long long addf2(unsigned long long a,
                                                    unsigned long long b) {
    unsigned long long r;
    asm("add.rn.f32x2 %0, %1, %2;" : "=l"(r) : "l"(a), "l"(b));
    return r;
}
__device__ __forceinline__ float2 unpack2(unsigned long long v) {
    float2 f;
    asm("mov.b64 {%0, %1}, %2;" : "=f"(f.x), "=f"(f.y) : "l"(v));
    return f;
}

__global__ void __launch_bounds__(NT, 1)
rnn_persistent(const float* __restrict__ x,
               const float* __restrict__ h_t,
               const float* __restrict__ Wih0, const float* __restrict__ Whh0,
               const float* __restrict__ bih0, const float* __restrict__ bhh0,
               const float* __restrict__ Wih1, const float* __restrict__ Whh1,
               const float* __restrict__ bih1, const float* __restrict__ bhh1,
               float* __restrict__ out) {
    // A staged as duplicated float2 {a,a}: one LDS.64 == packed broadcast.
    // Rows padded to 33 float2 (conflict-free); all smem A writes are float2
    // (8B-aligned) because odd rows start on 8B-but-not-16B boundaries.
    __shared__ float2 A2_s[2][BB][KB + 1];
    __shared__ unsigned long long Red[3][128][4];
    __shared__ float bsum[16];

    const int tid    = threadIdx.x;
    const int stage  = blockIdx.x >> 5;   // 0:P0 xproj  1:S0 rec0  2:P1 proj1  3:S1 rec1
    const int cb     = blockIdx.x & 31;
    const int c_base = cb * 16;

    const int kq  = tid >> 7;     // 0..3  K-quarter (warp-uniform)
    const int pos = tid & 127;
    const int ri  = pos >> 2;     // 0..31 row-pair index
    const int ci  = pos & 3;      // 0..3  col-quad index
    const int r0  = ri * 2;       // 2 rows per thread
    const int c0  = ci * 4;       // 4 cols per thread (2 packed pairs)

    const float* Wm = (stage == 0) ? Wih0 : (stage == 1) ? Whh0
                    : (stage == 2) ? Wih1 : Whh1;

    if (tid < 16) {
        float bv = 0.f;
        if (stage == 0)      bv = bih0[c_base + tid] + bhh0[c_base + tid];
        else if (stage == 2) bv = bih1[c_base + tid] + bhh1[c_base + tid];
        bsum[tid] = bv;
    }

    // Init hidden states from h_t [2,B,H]
    {
        int gid = blockIdx.x * NT + tid;
        if (gid < (BB * HH) / 4) {
            float4 v0 = __ldg((const float4*)h_t + gid);
            float4 v1 = __ldg((const float4*)(h_t + BB * HH) + gid);
            __stcg((float4*)&g_h0[0][0] + gid, v0);
            __stcg((float4*)&g_h1[0][0] + gid, v1);
        }
    }

    unsigned bar = 1;
    grid_sync(bar * NB); bar++;

    // Staging coords: each thread loads exactly ONE float4 per 32-wide k-block
    // (64 rows x 8 float4 = 512 = NT), writes it duplicated as four float2s.
    const int sb  = tid >> 3;     // row 0..63
    const int sk4 = tid & 7;      // float4 id within 32-wide block

    for (int it = 0; it <= TT + 2; ++it) {
        int t; bool active; const float* Ain;
        if (stage == 0)      { t = it;     active = (t < TT);            Ain = x + (size_t)(t < TT ? t : 0) * BB * DD; }
        else if (stage == 1) { t = it - 1; active = (t >= 0 && t < TT);  Ain = g_h0[t & 1]; }
        else if (stage == 2) { t = it - 2; active = (t >= 0 && t < TT);  Ain = g_h0[(t + 1) & 1]; }
        else                 { t = it - 3; active = (t >= 0 && t < TT);  Ain = g_h1[t & 1]; }

        if (active) {
            unsigned long long acc[2][2];   // [row][colpair]
            acc[0][0] = acc[0][1] = acc[1][0] = acc[1][1] = 0ull;

            const float4* arow = (const float4*)(Ain + sb * 512) + sk4;

            // Distance-2 register prefetch pipeline over 16 k-blocks
            float4 preA = __ldcg(arow);                 // kb 0
            {
                float2* d = &A2_s[0][sb][sk4 * 4];
                d[0] = make_float2(preA.x, preA.x);
                d[1] = make_float2(preA.y, preA.y);
                d[2] = make_float2(preA.z, preA.z);
                d[3] = make_float2(preA.w, preA.w);
            }
            preA = __ldcg(arow + 8);                    // kb 1 (each kb = 8 float4s)
            __syncthreads();

            #pragma unroll 1
            for (int kb = 0; kb < NKB; ++kb) {
                const int cur = kb & 1;
                float4 preB;
                if (kb + 2 < NKB) preB = __ldcg(arow + (kb + 2) * 8);

                const float* wp = Wm + (size_t)(kb * KB + kq * 8) * HH + c_base + c0;
                #pragma unroll
                for (int kk = 0; kk < 8; ++kk) {
                    const int kl = kq * 8 + kk;
                    ulonglong2 wv = __ldg((const ulonglong2*)(wp + (size_t)kk * HH));
                    unsigned long long a0 = *(const unsigned long long*)&A2_s[cur][r0 + 0][kl];
                    unsigned long long a1 = *(const unsigned long long*)&A2_s[cur][r0 + 1][kl];
                    ffma2(acc[0][0], a0, wv.x); ffma2(acc[0][1], a0, wv.y);
                    ffma2(acc[1][0], a1, wv.x); ffma2(acc[1][1], a1, wv.y);
                }

                if (kb + 1 < NKB) {
                    float2* d = &A2_s[cur ^ 1][sb][sk4 * 4];
                    d[0] = make_float2(preA.x, preA.x);
                    d[1] = make_float2(preA.y, preA.y);
                    d[2] = make_float2(preA.z, preA.z);
                    d[3] = make_float2(preA.w, preA.w);
                    preA = preB;
                }
                __syncthreads();
            }

            // Reduce across the 4 K-quarters (packed adds)
            if (kq != 0) {
                #pragma unroll
                for (int i = 0; i < 2; ++i) {
                    Red[kq - 1][pos][i * 2 + 0] = acc[i][0];
                    Red[kq - 1][pos][i * 2 + 1] = acc[i][1];
                }
            }
            __syncthreads();

            if (kq == 0) {
                #pragma unroll
                for (int i = 0; i < 2; ++i) {
                    #pragma unroll
                    for (int p = 0; p < 2; ++p) {
                        unsigned long long s = acc[i][p];
                        s = addf2(s, Red[0][pos][i * 2 + p]);
                        s = addf2(s, Red[1][pos][i * 2 + p]);
                        s = addf2(s, Red[2][pos][i * 2 + p]);
                        acc[i][p] = s;
                    }
                }

                float* dst;
                const float* xwsrc = nullptr;
                float* dst2 = nullptr;
                if (stage == 0)      { dst = g_xw0[it & 1]; }
                else if (stage == 1) { xwsrc = g_xw0[t & 1]; dst = g_h0[(t + 1) & 1]; }
                else if (stage == 2) { dst = g_xw1[t & 1]; }
                else                 { xwsrc = g_xw1[t & 1]; dst = g_h1[(t + 1) & 1];
                                       dst2 = out + (size_t)t * BB * HH; }
                const bool dotanh = (stage & 1);

                #pragma unroll
                for (int ir = 0; ir < 2; ++ir) {
                    int off = (r0 + ir) * HH + c_base + c0;
                    float2 lo = unpack2(acc[ir][0]);
                    float2 hi = unpack2(acc[ir][1]);
                    float v0 = lo.x, v1 = lo.y, v2 = hi.x, v3 = hi.y;
                    if (dotanh) {
                        float4 xw = __ldcg((const float4*)(xwsrc + off));
                        v0 = tanhf(v0 + xw.x);
                        v1 = tanhf(v1 + xw.y);
                        v2 = tanhf(v2 + xw.z);
                        v3 = tanhf(v3 + xw.w);
                    } else {
                        v0 += bsum[c0 + 0];
                        v1 += bsum[c0 + 1];
                        v2 += bsum[c0 + 2];
                        v3 += bsum[c0 + 3];
                    }
                    float4 o = make_float4(v0, v1, v2, v3);
                    __stcg((float4*)(dst + off), o);
                    if (dst2) *(float4*)(dst2 + off) = o;
                }
            }
        }

        grid_sync(bar * NB); bar++;
    }

    // Final hidden states -> out[T*B*H ..]; both layers end in slot (T & 1) == 0
    {
        int gid = blockIdx.x * NT + tid;
        if (gid < (BB * HH) / 4) {
            float4 a = __ldcg((const float4*)&g_h0[0][0] + gid);
            float4 b = __ldcg((const float4*)&g_h1[0][0] + gid);
            *((float4*)(out + (size_t)TT * BB * HH) + gid) = a;
            *((float4*)(out + (size_t)TT * BB * HH + BB * HH) + gid) = b;
        }
    }
}

extern "C" void kernel_launch(void* const* d_in, const int* in_sizes, int n_in,
                              void* d_out, int out_size) {
    (void)in_sizes; (void)n_in; (void)out_size;
    const float* x    = (const float*)d_in[0];
    const float* h_t  = (const float*)d_in[1];
    const float* Wih0 = (const float*)d_in[2];
    const float* Whh0 = (const float*)d_in[3];
    const float* bih0 = (const float*)d_in[4];
    const float* bhh0 = (const float*)d_in[5];
    const float* Wih1 = (const float*)d_in[6];
    const float* Whh1 = (const float*)d_in[7];
    const float* bih1 = (const float*)d_in[8];
    const float* bhh1 = (const float*)d_in[9];
    float* out = (float*)d_out;

    rnn_reset_kernel<<<1, 1>>>();
    rnn_persistent<<<NB, NT>>>(x, h_t, Wih0, Whh0, bih0, bhh0,
                               Wih1, Whh1, bih1, bhh1, out);
}

// round 10
// speedup vs baseline: 1.3755x; 1.3755x over previous
#include <cuda_runtime.h>
#include <math.h>

// Problem constants
#define TT   1024
#define BB   64
#define DD   512
#define HH   512

// Kernel config
#define NB   128      // CTAs: 4 stages x 32 column-blocks (co-resident on <=148 SMs)
#define NT   512      // threads per CTA (16 warps -> 4 per SMSP)
#define KB   64       // K-block staged in smem (double-buffered)
#define NKB  8        // 512 / 64

// -------- device scratch (no allocations allowed) --------
__device__ __align__(16) float g_xw0[2][BB * HH];
__device__ __align__(16) float g_xw1[2][BB * HH];
__device__ __align__(16) float g_h0[2][BB * HH];
__device__ __align__(16) float g_h1[2][BB * HH];
__device__ unsigned g_count;

__global__ void rnn_reset_kernel() { g_count = 0u; }

__device__ __forceinline__ void grid_sync(unsigned target) {
    __syncthreads();
    if (threadIdx.x == 0) {
        __threadfence();                 // release all prior global writes
        atomicAdd(&g_count, 1u);
        unsigned v;
        do {
            asm volatile("ld.acquire.gpu.u32 %0, [%1];" : "=r"(v) : "l"(&g_count));
        } while (v < target);
    }
    __syncthreads();
}

__global__ void __launch_bounds__(NT, 1)
rnn_persistent(const float* __restrict__ x,
               const float* __restrict__ h_t,
               const float* __restrict__ Wih0, const float* __restrict__ Whh0,
               const float* __restrict__ bih0, const float* __restrict__ bhh0,
               const float* __restrict__ Wih1, const float* __restrict__ Whh1,
               const float* __restrict__ bih1, const float* __restrict__ bhh1,
               float* __restrict__ out) {
    // A_s: 2 x 64 x 65 floats = 33,280 B (padded rows: conflict-free column reads).
    // Red: 3 x 128 x 8 floats  = 12,288 B. Total static smem ~45.6 KB < 48 KB.
    __shared__ float A_s[2][BB][KB + 1];
    __shared__ float Red[3][128][8];
    __shared__ float bsum[16];

    const int tid    = threadIdx.x;
    const int stage  = blockIdx.x >> 5;   // 0:P0 xproj  1:S0 rec0  2:P1 proj1  3:S1 rec1
    const int cb     = blockIdx.x & 31;
    const int c_base = cb * 16;

    const int kq  = tid >> 7;     // 0..3  K-quarter (warp-uniform)
    const int pos = tid & 127;
    const int ri  = pos >> 2;     // 0..31 row-pair index
    const int ci  = pos & 3;      // 0..3  col-quad index
    const int r0  = ri * 2;       // 2 rows per thread
    const int c0  = ci * 4;       // 4 cols per thread

    const float* Wm = (stage == 0) ? Wih0 : (stage == 1) ? Whh0
                    : (stage == 2) ? Wih1 : Whh1;

    if (tid < 16) {
        float bv = 0.f;
        if (stage == 0)      bv = bih0[c_base + tid] + bhh0[c_base + tid];
        else if (stage == 2) bv = bih1[c_base + tid] + bhh1[c_base + tid];
        bsum[tid] = bv;
    }

    // Init hidden states from h_t [2,B,H]
    {
        int gid = blockIdx.x * NT + tid;
        if (gid < (BB * HH) / 4) {
            float4 v0 = __ldg((const float4*)h_t + gid);
            float4 v1 = __ldg((const float4*)(h_t + BB * HH) + gid);
            __stcg((float4*)&g_h0[0][0] + gid, v0);
            __stcg((float4*)&g_h1[0][0] + gid, v1);
        }
    }

    unsigned bar = 1;
    grid_sync(bar * NB); bar++;

    // Staging coords: 64 rows x 16 float4 = 1024 float4 per 64-wide k-block;
    // 512 threads -> 2 float4 each.
    int sb[2], sk4[2];
    #pragma unroll
    for (int j = 0; j < 2; ++j) {
        int q = tid + NT * j;       // 0..1023
        sb[j]  = q >> 4;            // row 0..63
        sk4[j] = q & 15;            // float4 within 64-wide block
    }

    for (int it = 0; it <= TT + 2; ++it) {
        int t; bool active; const float* Ain;
        if (stage == 0)      { t = it;     active = (t < TT);            Ain = x + (size_t)(t < TT ? t : 0) * BB * DD; }
        else if (stage == 1) { t = it - 1; active = (t >= 0 && t < TT);  Ain = g_h0[t & 1]; }
        else if (stage == 2) { t = it - 2; active = (t >= 0 && t < TT);  Ain = g_h0[(t + 1) & 1]; }
        else                 { t = it - 3; active = (t >= 0 && t < TT);  Ain = g_h1[t & 1]; }

        if (active) {
            float acc[2][4];
            #pragma unroll
            for (int i = 0; i < 2; ++i)
                #pragma unroll
                for (int j = 0; j < 4; ++j) acc[i][j] = 0.f;

            float4 pre[2];
            // Prologue: fetch k-block 0 into buffer 0
            #pragma unroll
            for (int j = 0; j < 2; ++j)
                pre[j] = __ldcg((const float4*)(Ain + sb[j] * 512) + sk4[j]);
            #pragma unroll
            for (int j = 0; j < 2; ++j) {
                float* d = &A_s[0][sb[j]][sk4[j] * 4];
                d[0] = pre[j].x; d[1] = pre[j].y; d[2] = pre[j].z; d[3] = pre[j].w;
            }
            __syncthreads();

            for (int kb = 0; kb < NKB; ++kb) {
                const int cur = kb & 1;
                // Prefetch next block into registers while computing this one
                if (kb + 1 < NKB) {
                    #pragma unroll
                    for (int j = 0; j < 2; ++j)
                        pre[j] = __ldcg((const float4*)(Ain + sb[j] * 512 + (kb + 1) * KB) + sk4[j]);
                }

                const float* wp = Wm + (size_t)(kb * KB + kq * 16) * HH + c_base + c0;
                #pragma unroll
                for (int kk = 0; kk < 16; ++kk) {
                    const int kl = kq * 16 + kk;
                    float4 w = __ldg((const float4*)(wp + (size_t)kk * HH));
                    float a0 = A_s[cur][r0 + 0][kl];
                    float a1 = A_s[cur][r0 + 1][kl];
                    acc[0][0] += a0 * w.x; acc[0][1] += a0 * w.y; acc[0][2] += a0 * w.z; acc[0][3] += a0 * w.w;
                    acc[1][0] += a1 * w.x; acc[1][1] += a1 * w.y; acc[1][2] += a1 * w.z; acc[1][3] += a1 * w.w;
                }

                // Store prefetched block into the other buffer, then one sync
                if (kb + 1 < NKB) {
                    #pragma unroll
                    for (int j = 0; j < 2; ++j) {
                        float* d = &A_s[cur ^ 1][sb[j]][sk4[j] * 4];
                        d[0] = pre[j].x; d[1] = pre[j].y; d[2] = pre[j].z; d[3] = pre[j].w;
                    }
                }
                __syncthreads();
            }

            // Reduce across the 4 K-quarters
            if (kq != 0) {
                #pragma unroll
                for (int i = 0; i < 2; ++i)
                    #pragma unroll
                    for (int j = 0; j < 4; ++j)
                        Red[kq - 1][pos][i * 4 + j] = acc[i][j];
            }
            __syncthreads();

            if (kq == 0) {
                #pragma unroll
                for (int i = 0; i < 2; ++i)
                    #pragma unroll
                    for (int j = 0; j < 4; ++j)
                        acc[i][j] += Red[0][pos][i * 4 + j]
                                   + Red[1][pos][i * 4 + j]
                                   + Red[2][pos][i * 4 + j];

                float* dst;
                const float* xwsrc = nullptr;
                float* dst2 = nullptr;
                if (stage == 0)      { dst = g_xw0[it & 1]; }
                else if (stage == 1) { xwsrc = g_xw0[t & 1]; dst = g_h0[(t + 1) & 1]; }
                else if (stage == 2) { dst = g_xw1[t & 1]; }
                else                 { xwsrc = g_xw1[t & 1]; dst = g_h1[(t + 1) & 1];
                                       dst2 = out + (size_t)t * BB * HH; }
                const bool dotanh = (stage & 1);

                #pragma unroll
                for (int ir = 0; ir < 2; ++ir) {
                    int off = (r0 + ir) * HH + c_base + c0;
                    float v0 = acc[ir][0], v1 = acc[ir][1], v2 = acc[ir][2], v3 = acc[ir][3];
                    if (dotanh) {
                        float4 xw = __ldcg((const float4*)(xwsrc + off));
                        v0 = tanhf(v0 + xw.x);
                        v1 = tanhf(v1 + xw.y);
                        v2 = tanhf(v2 + xw.z);
                        v3 = tanhf(v3 + xw.w);
                    } else {
                        v0 += bsum[c0 + 0];
                        v1 += bsum[c0 + 1];
                        v2 += bsum[c0 + 2];
                        v3 += bsum[c0 + 3];
                    }
                    float4 o = make_float4(v0, v1, v2, v3);
                    __stcg((float4*)(dst + off), o);
                    if (dst2) *(float4*)(dst2 + off) = o;
                }
            }
        }

        grid_sync(bar * NB); bar++;
    }

    // Final hidden states -> out[T*B*H ..]; both layers end in slot (T & 1) == 0
    {
        int gid = blockIdx.x * NT + tid;
        if (gid < (BB * HH) / 4) {
            float4 a = __ldcg((const float4*)&g_h0[0][0] + gid);
            float4 b = __ldcg((const float4*)&g_h1[0][0] + gid);
            *((float4*)(out + (size_t)TT * BB * HH) + gid) = a;
            *((float4*)(out + (size_t)TT * BB * HH + BB * HH) + gid) = b;
        }
    }
}

extern "C" void kernel_launch(void* const* d_in, const int* in_sizes, int n_in,
                              void* d_out, int out_size) {
    (void)in_sizes; (void)n_in; (void)out_size;
    const float* x    = (const float*)d_in[0];
    const float* h_t  = (const float*)d_in[1];
    const float* Wih0 = (const float*)d_in[2];
    const float* Whh0 = (const float*)d_in[3];
    const float* bih0 = (const float*)d_in[4];
    const float* bhh0 = (const float*)d_in[5];
    const float* Wih1 = (const float*)d_in[6];
    const float* Whh1 = (const float*)d_in[7];
    const float* bih1 = (const float*)d_in[8];
    const float* bhh1 = (const float*)d_in[9];
    float* out = (float*)d_out;

    rnn_reset_kernel<<<1, 1>>>();
    rnn_persistent<<<NB, NT>>>(x, h_t, Wih0, Whh0, bih0, bhh0,
                               Wih1, Whh1, bih1, bhh1, out);
}

// round 11
// speedup vs baseline: 1.3921x; 1.0121x over previous
#include <cuda_runtime.h>
#include <math.h>

// Problem constants
#define TT   1024
#define BB   64
#define DD   512
#define HH   512

// Kernel config
#define NB   128      // 4 stages x 32 column-blocks (co-resident on <=148 SMs)
#define NT   256      // threads per CTA
#define KB   64       // K-block staged in smem (double-buffered)
#define NKB  8        // 512 / 64
#define DEPTH 4       // ring-buffer depth between stages

// -------- device scratch (no allocations allowed) --------
__device__ __align__(16) float g_xw0[DEPTH][BB * HH];
__device__ __align__(16) float g_xw1[DEPTH][BB * HH];
__device__ __align__(16) float g_h0[DEPTH][BB * HH];
__device__ __align__(16) float g_h1[DEPTH][BB * HH];
__device__ unsigned g_count;
__device__ __align__(128) unsigned g_cnt[4 * 32];   // stage s counter at g_cnt[s*32]

__global__ void rnn_reset_kernel() {
    g_count = 0u;
    for (int s = 0; s < 4; ++s) g_cnt[s * 32] = 0u;
}

__device__ __forceinline__ void wait_ge(const unsigned* addr, unsigned target) {
    unsigned v;
    do {
        asm volatile("ld.acquire.gpu.u32 %0, [%1];" : "=r"(v) : "l"(addr));
    } while (v < target);
}

__device__ __forceinline__ void grid_sync_once(unsigned target) {
    __syncthreads();
    if (threadIdx.x == 0) {
        __threadfence();
        atomicAdd(&g_count, 1u);
        unsigned v;
        do {
            asm volatile("ld.acquire.gpu.u32 %0, [%1];" : "=r"(v) : "l"(&g_count));
        } while (v < target);
    }
    __syncthreads();
}

__global__ void __launch_bounds__(NT, 1)
rnn_persistent(const float* __restrict__ x,
               const float* __restrict__ h_t,
               const float* __restrict__ Wih0, const float* __restrict__ Whh0,
               const float* __restrict__ bih0, const float* __restrict__ bhh0,
               const float* __restrict__ Wih1, const float* __restrict__ Whh1,
               const float* __restrict__ bih1, const float* __restrict__ bhh1,
               float* __restrict__ out) {
    __shared__ float A_s[2][BB][KB + 1];
    __shared__ float Red[3][64][16];
    __shared__ float bsum[16];

    const int tid    = threadIdx.x;
    const int stage  = blockIdx.x >> 5;   // 0:P0 xproj  1:S0 rec0  2:P1 proj1  3:S1 rec1
    const int cb     = blockIdx.x & 31;
    const int c_base = cb * 16;

    const int kq  = tid >> 6;     // 0..3  K-quarter
    const int pos = tid & 63;
    const int ri  = pos >> 2;     // 0..15 row-block
    const int ci  = pos & 3;      // 0..3  col-block
    const int r0  = ri * 4;
    const int c0  = ci * 4;

    const float* Wm = (stage == 0) ? Wih0 : (stage == 1) ? Whh0
                    : (stage == 2) ? Wih1 : Whh1;

    const unsigned* cP0 = &g_cnt[0];
    const unsigned* cS0 = &g_cnt[32];
    const unsigned* cP1 = &g_cnt[64];
    const unsigned* cS1 = &g_cnt[96];
    unsigned* myCnt = &g_cnt[stage * 32];

    if (tid < 16) {
        float bv = 0.f;
        if (stage == 0)      bv = bih0[c_base + tid] + bhh0[c_base + tid];
        else if (stage == 2) bv = bih1[c_base + tid] + bhh1[c_base + tid];
        bsum[tid] = bv;
    }

    // Init hidden states h[-1] into ring slot 3 (= (-1) mod 4)
    {
        int gid = blockIdx.x * NT + tid;
        if (gid < (BB * HH) / 4) {
            float4 v0 = __ldg((const float4*)h_t + gid);
            float4 v1 = __ldg((const float4*)(h_t + BB * HH) + gid);
            __stcg((float4*)&g_h0[3][0] + gid, v0);
            __stcg((float4*)&g_h1[3][0] + gid, v1);
        }
    }
    grid_sync_once(NB);   // one-time: init visible everywhere

    // Per-thread staging coordinates (4 float4 per thread per 64-wide k-block)
    int sb[4], sk4[4];
    #pragma unroll
    for (int j = 0; j < 4; ++j) {
        int q = tid + NT * j;       // 0..1023
        sb[j]  = q >> 4;            // row 0..63
        sk4[j] = q & 15;            // float4 within 64-wide block
    }

    for (int t = 0; t < TT; ++t) {
        // ---- dependency waits (thread 0 spins, CTA joins at syncthreads) ----
        if (tid == 0) {
            if (stage == 0) {
                if (t >= DEPTH) wait_ge(cS0, 32u * (unsigned)(t - 3));   // slot freed
            } else if (stage == 1) {
                wait_ge(cP0, 32u * (unsigned)(t + 1));                   // xw0[t] ready
                if (t)           wait_ge(cS0, 32u * (unsigned)t);        // h0[t-1] ready
                if (t >= DEPTH)  wait_ge(cP1, 32u * (unsigned)(t - 3));  // slot freed
            } else if (stage == 2) {
                wait_ge(cS0, 32u * (unsigned)(t + 1));                   // h0[t] ready
                if (t >= DEPTH)  wait_ge(cS1, 32u * (unsigned)(t - 3));  // slot freed
            } else {
                wait_ge(cP1, 32u * (unsigned)(t + 1));                   // xw1[t] ready
                if (t)           wait_ge(cS1, 32u * (unsigned)t);        // h1[t-1] ready
            }
        }
        __syncthreads();

        const float* Ain = (stage == 0) ? (x + (size_t)t * BB * DD)
                         : (stage == 1) ? g_h0[(t + 3) & 3]
                         : (stage == 2) ? g_h0[t & 3]
                         :                g_h1[(t + 3) & 3];

        float acc[4][4];
        #pragma unroll
        for (int i = 0; i < 4; ++i)
            #pragma unroll
            for (int j = 0; j < 4; ++j) acc[i][j] = 0.f;

        float4 pre[4];
        // Prologue: fetch k-block 0 into buffer 0
        #pragma unroll
        for (int j = 0; j < 4; ++j)
            pre[j] = __ldcg((const float4*)(Ain + sb[j] * 512) + sk4[j]);
        #pragma unroll
        for (int j = 0; j < 4; ++j) {
            float* d = &A_s[0][sb[j]][sk4[j] * 4];
            d[0] = pre[j].x; d[1] = pre[j].y; d[2] = pre[j].z; d[3] = pre[j].w;
        }
        __syncthreads();

        for (int kb = 0; kb < NKB; ++kb) {
            const int cur = kb & 1;
            if (kb + 1 < NKB) {
                #pragma unroll
                for (int j = 0; j < 4; ++j)
                    pre[j] = __ldcg((const float4*)(Ain + sb[j] * 512 + (kb + 1) * KB) + sk4[j]);
            }

            const float* wp = Wm + (size_t)(kb * KB + kq * 16) * HH + c_base + c0;
            #pragma unroll
            for (int kk = 0; kk < 16; ++kk) {
                const int kl = kq * 16 + kk;
                float4 w = __ldg((const float4*)(wp + (size_t)kk * HH));
                float a0 = A_s[cur][r0 + 0][kl];
                float a1 = A_s[cur][r0 + 1][kl];
                float a2 = A_s[cur][r0 + 2][kl];
                float a3 = A_s[cur][r0 + 3][kl];
                acc[0][0] += a0 * w.x; acc[0][1] += a0 * w.y; acc[0][2] += a0 * w.z; acc[0][3] += a0 * w.w;
                acc[1][0] += a1 * w.x; acc[1][1] += a1 * w.y; acc[1][2] += a1 * w.z; acc[1][3] += a1 * w.w;
                acc[2][0] += a2 * w.x; acc[2][1] += a2 * w.y; acc[2][2] += a2 * w.z; acc[2][3] += a2 * w.w;
                acc[3][0] += a3 * w.x; acc[3][1] += a3 * w.y; acc[3][2] += a3 * w.z; acc[3][3] += a3 * w.w;
            }

            if (kb + 1 < NKB) {
                #pragma unroll
                for (int j = 0; j < 4; ++j) {
                    float* d = &A_s[cur ^ 1][sb[j]][sk4[j] * 4];
                    d[0] = pre[j].x; d[1] = pre[j].y; d[2] = pre[j].z; d[3] = pre[j].w;
                }
            }
            __syncthreads();
        }

        // Reduce across the 4 K-quarters
        if (kq != 0) {
            #pragma unroll
            for (int i = 0; i < 4; ++i)
                #pragma unroll
                for (int j = 0; j < 4; ++j)
                    Red[kq - 1][pos][i * 4 + j] = acc[i][j];
        }
        __syncthreads();

        if (kq == 0) {
            #pragma unroll
            for (int i = 0; i < 4; ++i)
                #pragma unroll
                for (int j = 0; j < 4; ++j)
                    acc[i][j] += Red[0][pos][i * 4 + j]
                               + Red[1][pos][i * 4 + j]
                               + Red[2][pos][i * 4 + j];

            float* dst;
            const float* xwsrc = nullptr;
            float* dst2 = nullptr;
            float* dst3 = nullptr;
            if (stage == 0)      { dst = g_xw0[t & 3]; }
            else if (stage == 1) { xwsrc = g_xw0[t & 3]; dst = g_h0[t & 3];
                                   if (t == TT - 1) dst3 = out + (size_t)TT * BB * HH; }
            else if (stage == 2) { dst = g_xw1[t & 3]; }
            else                 { xwsrc = g_xw1[t & 3]; dst = g_h1[t & 3];
                                   dst2 = out + (size_t)t * BB * HH;
                                   if (t == TT - 1) dst3 = out + (size_t)TT * BB * HH + BB * HH; }
            const bool dotanh = (stage & 1);

            #pragma unroll
            for (int ir = 0; ir < 4; ++ir) {
                int off = (r0 + ir) * HH + c_base + c0;
                float v0 = acc[ir][0], v1 = acc[ir][1], v2 = acc[ir][2], v3 = acc[ir][3];
                if (dotanh) {
                    float4 xw = __ldcg((const float4*)(xwsrc + off));
                    v0 = tanhf(v0 + xw.x);
                    v1 = tanhf(v1 + xw.y);
                    v2 = tanhf(v2 + xw.z);
                    v3 = tanhf(v3 + xw.w);
                } else {
                    v0 += bsum[c0 + 0];
                    v1 += bsum[c0 + 1];
                    v2 += bsum[c0 + 2];
                    v3 += bsum[c0 + 3];
                }
                float4 o = make_float4(v0, v1, v2, v3);
                __stcg((float4*)(dst + off), o);
                if (dst2) *(float4*)(dst2 + off) = o;
                if (dst3) *(float4*)(dst3 + off) = o;
            }
        }
        __syncthreads();   // epilogue stores complete before posting

        if (tid == 0) {
            __threadfence();
            atomicAdd(myCnt, 1u);
        }
    }
}

extern "C" void kernel_launch(void* const* d_in, const int* in_sizes, int n_in,
                              void* d_out, int out_size) {
    (void)in_sizes; (void)n_in; (void)out_size;
    const float* x    = (const float*)d_in[0];
    const float* h_t  = (const float*)d_in[1];
    const float* Wih0 = (const float*)d_in[2];
    const float* Whh0 = (const float*)d_in[3];
    const float* bih0 = (const float*)d_in[4];
    const float* bhh0 = (const float*)d_in[5];
    const float* Wih1 = (const float*)d_in[6];
    const float* Whh1 = (const float*)d_in[7];
    const float* bih1 = (const float*)d_in[8];
    const float* bhh1 = (const float*)d_in[9];
    float* out = (float*)d_out;

    rnn_reset_kernel<<<1, 1>>>();
    rnn_persistent<<<NB, NT>>>(x, h_t, Wih0, Whh0, bih0, bhh0,
                               Wih1, Whh1, bih1, bhh1, out);
}